// round 17
// baseline (speedup 1.0000x reference)
#include <cuda_runtime.h>
#include <cstdint>

// PWC-Net correlation, B=8, C=128, H=112, W=192, 81 disps (dy,dx in [-4,4]).
// Round 17: R16 (no pad buffer, zero-quad pointer trick, h-pair register
// blocking, distance-1 V prefetch) + a minimal L2 prefetch of the `first`
// rows at distance 2: lanes 0-11 each prefetch one 128B line of F(c+2)
// (2 rows x 768B contiguous = 12 lines). F is CTA-private and DRAM-cold, and
// all 15 warps stall on the same F lines each channel -- this converts that
// correlated 577-cyc DRAM stall into a ~234-cyc L2 hit. +2 regs, 1 instr/body.

#define B_ 8
#define C_ 128
#define H_ 112
#define W_ 192
#define HW_ (H_ * W_)

typedef unsigned long long ull;

__device__ __align__(16) float g_zero[4];   // zero-initialized

__device__ __forceinline__ void fma2(ull& acc, ull a, ull b) {
    asm("fma.rn.f32x2 %0, %1, %2, %0;" : "+l"(acc) : "l"(a), "l"(b));
}
__device__ __forceinline__ void mul2(ull& v, ull s) {
    asm("mul.rn.f32x2 %0, %0, %1;" : "+l"(v) : "l"(s));
}
__device__ __forceinline__ ull pack_hl(ull a, ull b) {   // (a.hi, b.lo)
    return (a >> 32) | (b << 32);
}
__device__ __forceinline__ ull swap2(ull a) {            // (a.hi, a.lo)
    return (a >> 32) | (a << 32);
}
__device__ __forceinline__ ull lo_(float x, float y) {
    return (ull)__float_as_uint(x) | ((ull)__float_as_uint(y) << 32);
}
__device__ __forceinline__ void pfl2(const void* p) {
    asm volatile("prefetch.global.L2 [%0];" :: "l"(p));
}

// FMA block for one channel: V0..V2 (12 second cols), F0/F1 (first rows h0,h0+1)
#define FMA_BLOCK(V0_, V1_, V2_, F0_, F1_) do {                              \
    const ull E0 = lo_(V0_.x, V0_.y), E1 = lo_(V0_.z, V0_.w);                \
    const ull E2 = lo_(V1_.x, V1_.y), E3 = lo_(V1_.z, V1_.w);                \
    const ull E4 = lo_(V2_.x, V2_.y), E5 = lo_(V2_.z, V2_.w);                \
    const ull p0a = lo_(F0_.x, F0_.y), p0b = lo_(F0_.z, F0_.w);              \
    const ull s0a = swap2(p0a),        s0b = swap2(p0b);                     \
    const ull p1a = lo_(F1_.x, F1_.y), p1b = lo_(F1_.z, F1_.w);              \
    const ull s1a = swap2(p1a),        s1b = swap2(p1b);                     \
    fma2(e0[0], p0a, E0);  fma2(a0[0], s0a, E0);                             \
    fma2(e0[1], p0a, E1);  fma2(a0[1], s0a, E1);                             \
    fma2(e0[2], p0a, E2);  fma2(a0[2], s0a, E2);                             \
    fma2(e0[3], p0a, E3);  fma2(a0[3], s0a, E3);                             \
    fma2(e0[4], p0a, E4);  fma2(a0[4], s0a, E4);                             \
    fma2(f0e[0], p0b, E1); fma2(f0a[0], s0b, E1);                            \
    fma2(f0e[1], p0b, E2); fma2(f0a[1], s0b, E2);                            \
    fma2(f0e[2], p0b, E3); fma2(f0a[2], s0b, E3);                            \
    fma2(f0e[3], p0b, E4); fma2(f0a[3], s0b, E4);                            \
    fma2(f0e[4], p0b, E5); fma2(f0a[4], s0b, E5);                            \
    fma2(e1[0], p1a, E0);  fma2(a1[0], s1a, E0);                             \
    fma2(e1[1], p1a, E1);  fma2(a1[1], s1a, E1);                             \
    fma2(e1[2], p1a, E2);  fma2(a1[2], s1a, E2);                             \
    fma2(e1[3], p1a, E3);  fma2(a1[3], s1a, E3);                             \
    fma2(e1[4], p1a, E4);  fma2(a1[4], s1a, E4);                             \
    fma2(f1e[0], p1b, E1); fma2(f1a[0], s1b, E1);                            \
    fma2(f1e[1], p1b, E2); fma2(f1a[1], s1b, E2);                            \
    fma2(f1e[2], p1b, E3); fma2(f1a[2], s1b, E3);                            \
    fma2(f1e[3], p1b, E4); fma2(f1a[3], s1b, E4);                            \
    fma2(f1e[4], p1b, E5); fma2(f1a[4], s1b, E5);                            \
} while (0)

__global__ __launch_bounds__(480, 1)
void corr81_kernel(const float* __restrict__ first,
                   const float* __restrict__ second,
                   float* __restrict__ out) {
    const int h0  = 2 * blockIdx.x;    // output rows h0, h0+1
    const int b   = blockIdx.y;
    const int tid = threadIdx.x;       // 0..479
    const int pq  = tid % 48;
    const int g   = tid / 48;          // 0..9: second row = h0 + g - 4
    const int w0  = 4 * pq;

    // set 0: output row h0, dy_pad = g      (store if g<=8)
    // set 1: output row h0+1, dy_pad = g-1  (store if g>=1)
    ull e0[5], a0[5], f0e[5], f0a[5];
    ull e1[5], a1[5], f1e[5], f1a[5];
#pragma unroll
    for (int m = 0; m < 5; m++) {
        e0[m]=0; a0[m]=0; f0e[m]=0; f0a[m]=0;
        e1[m]=0; a1[m]=0; f1e[m]=0; f1a[m]=0;
    }

    // V pointers: quads at cols w0-4 / w0 / w0+4 of second row y = h0+g-4.
    // Out-of-image quads -> static zero quad with stride 0 (exact pad semantics).
    const int  y   = h0 + g - 4;
    const bool yok = (y >= 0) && (y < H_);
    const float* rowb = second + ((size_t)(b * C_) * H_ + (yok ? y : 0)) * W_;
    const float4* zq  = reinterpret_cast<const float4*>(g_zero);

    const bool ok0 = yok && (w0 >= 4);
    const bool ok2 = yok && (w0 <= 184);
    const float4* p0 = ok0 ? reinterpret_cast<const float4*>(rowb + w0 - 4) : zq;
    const float4* p1 = yok ? reinterpret_cast<const float4*>(rowb + w0)     : zq;
    const float4* p2 = ok2 ? reinterpret_cast<const float4*>(rowb + w0 + 4) : zq;
    const int s0 = ok0 ? (int)(HW_ * sizeof(float)) : 0;   // byte strides
    const int s1 = yok ? (int)(HW_ * sizeof(float)) : 0;
    const int s2 = ok2 ? (int)(HW_ * sizeof(float)) : 0;

    const float4* fp = reinterpret_cast<const float4*>(
        first + ((size_t)(b * C_) * H_ + h0) * W_ + w0);

    // L2-prefetch pointer for F(c+2): rows h0,h0+1 are 1536B contiguous =
    // 12 lines; lane tid<12 prefetches line tid.
    const char* fpre = reinterpret_cast<const char*>(first)
        + (((size_t)(b * C_ + 2) * H_ + h0) * W_ + (size_t)tid * 32) * sizeof(float);

    // prologue: V for channel 0
    float4 V0 = *p0, V1 = *p1, V2 = *p2;

    for (int c = 0; c < C_ - 1; c++) {
        // unconditional advance (no select); loads channel c+1's V
        p0 = reinterpret_cast<const float4*>(reinterpret_cast<const char*>(p0) + s0);
        p1 = reinterpret_cast<const float4*>(reinterpret_cast<const char*>(p1) + s1);
        p2 = reinterpret_cast<const float4*>(reinterpret_cast<const char*>(p2) + s2);
        const float4 nV0 = *p0;
        const float4 nV1 = *p1;
        const float4 nV2 = *p2;

        const float4 F0 = fp[0];
        const float4 F1 = fp[W_ / 4];      // row h0+1: +768B immediate
        fp += HW_ / 4;

        // distance-2 L2 prefetch of F (12 lines, lanes 0-11, in-bounds: c+2<=127)
        if (tid < 12 && c < C_ - 2) pfl2(fpre);
        fpre += HW_ * sizeof(float);

        FMA_BLOCK(V0, V1, V2, F0, F1);

        V0 = nV0; V1 = nV1; V2 = nV2;
    }
    {   // peeled last channel (c = 127): no prefetch
        const float4 F0 = fp[0];
        const float4 F1 = fp[W_ / 4];
        FMA_BLOCK(V0, V1, V2, F0, F1);
    }

    const unsigned sb = __float_as_uint(1.0f / (float)C_);
    const ull scale2 = (ull)sb | ((ull)sb << 32);

    if (g <= 8) {   // set 0: channel g*9+dx at row h0
        float* od = out + (((size_t)(b * 81 + g * 9)) * H_ + h0) * W_ + w0;
#pragma unroll
        for (int m = 0; m < 5; m++) {
            ull va = e0[m];  mul2(va, scale2);
            ull vb = f0e[m]; mul2(vb, scale2);
            ulonglong2 pk; pk.x = va; pk.y = vb;
            *reinterpret_cast<ulonglong2*>(od + (size_t)(2 * m) * HW_) = pk;
        }
#pragma unroll
        for (int m = 0; m < 4; m++) {
            ull va = pack_hl(a0[m], a0[m + 1]); mul2(va, scale2);
            ull vb = pack_hl(f0a[m], f0a[m + 1]); mul2(vb, scale2);
            ulonglong2 pk; pk.x = va; pk.y = vb;
            *reinterpret_cast<ulonglong2*>(od + (size_t)(2 * m + 1) * HW_) = pk;
        }
    }
    if (g >= 1) {   // set 1: channel (g-1)*9+dx at row h0+1
        float* od = out + (((size_t)(b * 81 + (g - 1) * 9)) * H_ + (h0 + 1)) * W_ + w0;
#pragma unroll
        for (int m = 0; m < 5; m++) {
            ull va = e1[m];  mul2(va, scale2);
            ull vb = f1e[m]; mul2(vb, scale2);
            ulonglong2 pk; pk.x = va; pk.y = vb;
            *reinterpret_cast<ulonglong2*>(od + (size_t)(2 * m) * HW_) = pk;
        }
#pragma unroll
        for (int m = 0; m < 4; m++) {
            ull va = pack_hl(a1[m], a1[m + 1]); mul2(va, scale2);
            ull vb = pack_hl(f1a[m], f1a[m + 1]); mul2(vb, scale2);
            ulonglong2 pk; pk.x = va; pk.y = vb;
            *reinterpret_cast<ulonglong2*>(od + (size_t)(2 * m + 1) * HW_) = pk;
        }
    }
}

extern "C" void kernel_launch(void* const* d_in, const int* in_sizes, int n_in,
                              void* d_out, int out_size) {
    const float* first  = (const float*)d_in[0];
    const float* second = (const float*)d_in[1];
    float* out = (float*)d_out;

    dim3 grid(H_ / 2, B_);   // (56 h-pairs, 8 batches)
    corr81_kernel<<<grid, 480>>>(first, second, out);
}